// round 12
// baseline (speedup 1.0000x reference)
#include <cuda_runtime.h>

#define T_STEPS 500
#define N_NEUR  20000
#define NPAIR   (N_NEUR / 2)     // 10000 threads-worth of pairs
#define NGRP    313              // pair-groups of 32
#define NROLE3  245              // groups 0..244 get a 4th replica (1184 = 3*313 + 245)
#define DT      0.1f
#define UNROLL  10               // 500 = 10 * 50
#define NBLK    (T_STEPS / UNROLL)

__device__ __forceinline__ float fast_tanh(float t) {
    float r;
    asm("tanh.approx.f32 %0, %1;" : "=f"(r) : "f"(t));
    return r;
}

__device__ __forceinline__ void hh_step(
    float icur, float& V, float& p, float& q, float& nn, float& e, float& f, float& cac,
    float pc1, float pc0, float qc1, float qc0, float nc1, float nc0,
    float fc1, float fc0, float ec1, float ec0, float hc1, float hc0,
    float Ap, float Bp, float Aq, float Bq, float An, float Bn,
    float Af, float Bf, float Ae, float Be,
    float hb, float ha, float gCa, float gKs, float gKf, float gL,
    float ECa, float EK, float EL, float dtCm, float cdec, float rhoDt)
{
    const float h = fmaf(hb, fast_tanh(fmaf(cac, hc1, hc0)), ha);

    const float gef  = gCa * e * e * f * h;
    const float i_ca = gef * (V - ECa);
    const float VmEK = V - EK;
    const float i_ks = gKs * nn * VmEK;
    const float p2   = p * p;
    const float i_kf = gKf * p2 * p2 * q * VmEK;
    const float i_l  = gL * (V - EL);

    const float itot = icur - ((i_ca + i_ks) + (i_kf + i_l));
    const float dV   = itot * dtCm;
    V += dV;

    const float i_ca2 = fmaf(gef, dV, i_ca);       // gef*(V_new-ECa) identity
    cac = fmaf(cac, cdec, -i_ca2 * rhoDt);

    p  = fmaf(Bp, fast_tanh(fmaf(V, pc1, pc0)), fmaf(Ap, p,  Bp));
    q  = fmaf(Bq, fast_tanh(fmaf(V, qc1, qc0)), fmaf(Aq, q,  Bq));
    e  = fmaf(Be, fast_tanh(fmaf(V, ec1, ec0)), fmaf(Ae, e,  Be));
    f  = fmaf(Bf, fast_tanh(fmaf(V, fc1, fc0)), fmaf(Af, f,  Bf));
    nn = fmaf(Bn, fast_tanh(fmaf(V, nc1, nc0)), fmaf(An, nn, Bn));
}

__global__ void __launch_bounds__(32, 8) hh_kernel(
    const float* __restrict__ i_inj,   // [T, N]
    const float* __restrict__ x0,      // [7, N]
    const float* __restrict__ params,  // [28]
    float* __restrict__ out)           // [T, 7, N]
{
    // 1184 one-warp blocks = exactly 8/SM = 2/SMSP.
    // Roles per group: 0 -> stores V,p ; 1 -> q,n ; 2 -> e,f (+cac if no role 3)
    //                  3 (groups 0..244 only) -> cac
    const int bid = blockIdx.x;
    int grp, role;
    if (bid < 3 * NGRP) { role = bid / NGRP; grp = bid - role * NGRP; }
    else                { role = 3;          grp = bid - 3 * NGRP; }

    const bool sVp  = (role == 0);
    const bool sQn  = (role == 1);
    const bool sEf  = (role == 2);
    const bool sCac = (role == 3) || (role == 2 && grp >= NROLE3);

    const int pi = grp * 32 + threadIdx.x;
    if (pi >= NPAIR) return;
    const int n2 = 2 * pi;

    // ---- fold constants (identical on every replica -> identical trajectories)
    const float decay_ca = params[0];
    const float rho_ca   = params[1];
    const float p_tau = params[2],  p_scale = params[3],  p_mdp = params[4];
    const float q_tau = params[5],  q_scale = params[6],  q_mdp = params[7];
    const float n_tau = params[8],  n_scale = params[9],  n_mdp = params[10];
    const float f_tau = params[11], f_scale = params[12], f_mdp = params[13];
    const float e_tau = params[14], e_scale = params[15], e_mdp = params[16];
    const float h_alpha = params[17], h_scale = params[18], h_mdp = params[19];
    const float C_m = params[20], g_Ca = params[21], g_Ks = params[22];
    const float g_Kf = params[23], g_L = params[24];
    const float E_Ca = params[25], E_K = params[26], E_L = params[27];

    const float pc1 = 0.5f / p_scale, pc0 = -p_mdp * 0.5f / p_scale;
    const float qc1 = 0.5f / q_scale, qc0 = -q_mdp * 0.5f / q_scale;
    const float nc1 = 0.5f / n_scale, nc0 = -n_mdp * 0.5f / n_scale;
    const float fc1 = 0.5f / f_scale, fc0 = -f_mdp * 0.5f / f_scale;
    const float ec1 = 0.5f / e_scale, ec0 = -e_mdp * 0.5f / e_scale;
    const float hc1 = 0.5f / h_scale, hc0 = -h_mdp * 0.5f / h_scale;

    const float Ap = p_tau / (p_tau + DT), Bp = 0.5f * DT / (p_tau + DT);
    const float Aq = q_tau / (q_tau + DT), Bq = 0.5f * DT / (q_tau + DT);
    const float An = n_tau / (n_tau + DT), Bn = 0.5f * DT / (n_tau + DT);
    const float Af = f_tau / (f_tau + DT), Bf = 0.5f * DT / (f_tau + DT);
    const float Ae = e_tau / (e_tau + DT), Be = 0.5f * DT / (e_tau + DT);

    const float hb = 0.5f * h_alpha, ha = 1.0f - 0.5f * h_alpha;
    const float dtCm  = DT / C_m;
    const float cdec  = 1.0f - DT / decay_ca;
    const float rhoDt = rho_ca * DT;

    // ---- state: two adjacent neurons, independent chains a/b
    float Va = x0[0*N_NEUR+n2], Vb = x0[0*N_NEUR+n2+1];
    float pa = x0[1*N_NEUR+n2], pb = x0[1*N_NEUR+n2+1];
    float qa = x0[2*N_NEUR+n2], qb = x0[2*N_NEUR+n2+1];
    float na = x0[3*N_NEUR+n2], nb = x0[3*N_NEUR+n2+1];
    float ea = x0[4*N_NEUR+n2], eb = x0[4*N_NEUR+n2+1];
    float fa = x0[5*N_NEUR+n2], fb = x0[5*N_NEUR+n2+1];
    float ca = x0[6*N_NEUR+n2], cb = x0[6*N_NEUR+n2+1];

    const float* inj = i_inj + n2;
    float* o = out + n2;

    // ---- prefetch UNROLL currents (LDG.64 .ca -> replicas hit L2; MLP=10)
    float2 cur[UNROLL];
    #pragma unroll
    for (int u = 0; u < UNROLL; ++u)
        cur[u] = __ldg((const float2*)(inj + u * N_NEUR));
    inj += UNROLL * N_NEUR;

    #pragma unroll 1
    for (int blk = 0; blk < NBLK; ++blk) {
        float2 nxt[UNROLL];
        if (blk < NBLK - 1) {
            #pragma unroll
            for (int u = 0; u < UNROLL; ++u)
                nxt[u] = __ldg((const float2*)(inj + u * N_NEUR));
            inj += UNROLL * N_NEUR;
        }

        #pragma unroll
        for (int u = 0; u < UNROLL; ++u) {
            hh_step(cur[u].x, Va, pa, qa, na, ea, fa, ca,
                    pc1,pc0,qc1,qc0,nc1,nc0,fc1,fc0,ec1,ec0,hc1,hc0,
                    Ap,Bp,Aq,Bq,An,Bn,Af,Bf,Ae,Be,
                    hb,ha,g_Ca,g_Ks,g_Kf,g_L,E_Ca,E_K,E_L,dtCm,cdec,rhoDt);
            hh_step(cur[u].y, Vb, pb, qb, nb, eb, fb, cb,
                    pc1,pc0,qc1,qc0,nc1,nc0,fc1,fc0,ec1,ec0,hc1,hc0,
                    Ap,Bp,Aq,Bq,An,Bn,Af,Bf,Ae,Be,
                    hb,ha,g_Ca,g_Ks,g_Kf,g_L,E_Ca,E_K,E_L,dtCm,cdec,rhoDt);

            // role-split streaming stores (each replica ~2 STG.64/step)
            if (sVp) {
                __stcs((float2*)(o + 0*N_NEUR), make_float2(Va, Vb));
                __stcs((float2*)(o + 1*N_NEUR), make_float2(pa, pb));
            }
            if (sQn) {
                __stcs((float2*)(o + 2*N_NEUR), make_float2(qa, qb));
                __stcs((float2*)(o + 3*N_NEUR), make_float2(na, nb));
            }
            if (sEf) {
                __stcs((float2*)(o + 4*N_NEUR), make_float2(ea, eb));
                __stcs((float2*)(o + 5*N_NEUR), make_float2(fa, fb));
            }
            if (sCac) {
                __stcs((float2*)(o + 6*N_NEUR), make_float2(ca, cb));
            }
            o += 7 * N_NEUR;
        }

        #pragma unroll
        for (int u = 0; u < UNROLL; ++u)
            cur[u] = nxt[u];
    }
}

extern "C" void kernel_launch(void* const* d_in, const int* in_sizes, int n_in,
                              void* d_out, int out_size) {
    const float* i_inj  = (const float*)d_in[0];
    const float* x0     = (const float*)d_in[1];
    const float* params = (const float*)d_in[2];
    float* out = (float*)d_out;

    // 1184 one-warp blocks = 8 per SM = 2 per SMSP; 313 groups x 3-4 replicas,
    // stores split by role (bit-identical math -> deterministic output)
    hh_kernel<<<3 * NGRP + NROLE3, 32>>>(i_inj, x0, params, out);
}

// round 13
// speedup vs baseline: 1.2800x; 1.2800x over previous
#include <cuda_runtime.h>

#define T_STEPS 500
#define N_NEUR  20000
#define NPAIR   (N_NEUR / 2)     // 10000 pairs, 2 adjacent neurons each
#define NGRP    313              // pair-groups of 32
#define NREP    279              // groups 0..278 get a replica warp (592 total blocks)
#define DT      0.1f
#define UNROLL  10               // 500 = 10 * 50
#define NBLK    (T_STEPS / UNROLL)

__device__ __forceinline__ float fast_tanh(float t) {
    float r;
    asm("tanh.approx.f32 %0, %1;" : "=f"(r) : "f"(t));
    return r;
}

// one scalar HH step, dV-scaled algebra: every current is one FMA into acc.
__device__ __forceinline__ void hh_step(
    float icur, float& V, float& p, float& q, float& nn, float& e, float& f, float& cac,
    float pc1, float pc0, float qc1, float qc0, float nc1, float nc0,
    float fc1, float fc0, float ec1, float ec0, float hc1, float hc0,
    float Ap, float Bp, float Aq, float Bq, float An, float Bn,
    float Af, float Bf, float Ae, float Be,
    float hb, float ha,
    float gCad, float zk,      // z  = gCad*V + zk  = (V-E_Ca)*g_Ca*dt/Cm
    float gKsd, float uk,      // u  = gKsd*V + uk  = (V-E_K )*g_Ks*dt/Cm
    float rKfKs,               // v  = rKfKs*u      = (V-E_K )*g_Kf*dt/Cm
    float gLd, float gLdEL,    // leak: acc = fma(-gLd, V, acc), base += gLd*E_L
    float dtCm,
    float cA, float cB,        // zn' = cA*Vnew + cB = -rho*dt*g_Ca*(Vnew-E_Ca)
    float cdec)
{
    // h from OLD cac
    const float h = fmaf(hb, fast_tanh(fmaf(cac, hc1, hc0)), ha);

    // gate products
    const float e2 = e * e;
    const float m  = e2 * f * h;          // e^2*f*h (2 muls after e2)
    const float p2 = p * p;
    const float p4 = p2 * p2;
    const float w  = p4 * q;

    // dt/Cm-scaled driving terms (each one FMA of V)
    const float z = fmaf(gCad, V, zk);
    const float u = fmaf(gKsd, V, uk);
    const float v = rKfKs * u;

    // dV accumulator: acc = dtCm*icur + gLd*EL - gLd*V - m*z - nn*u - w*v
    float acc = fmaf(dtCm, icur, gLdEL);
    acc = fmaf(-gLd, V, acc);
    acc = fmaf(-m,  z, acc);
    acc = fmaf(-nn, u, acc);
    acc = fmaf(-w,  v, acc);
    V += acc;                              // acc IS dV

    // cac = cac*cdec - rho*dt*g_Ca*m*(Vnew-E_Ca)  (constants prefolded into cA,cB)
    const float znp = fmaf(cA, V, cB);
    cac = fmaf(cac, cdec, m * znp);

    // 5 independent gate chains on UPDATED V
    p  = fmaf(Bp, fast_tanh(fmaf(V, pc1, pc0)), fmaf(Ap, p,  Bp));
    q  = fmaf(Bq, fast_tanh(fmaf(V, qc1, qc0)), fmaf(Aq, q,  Bq));
    e  = fmaf(Be, fast_tanh(fmaf(V, ec1, ec0)), fmaf(Ae, e,  Be));
    f  = fmaf(Bf, fast_tanh(fmaf(V, fc1, fc0)), fmaf(Af, f,  Bf));
    nn = fmaf(Bn, fast_tanh(fmaf(V, nc1, nc0)), fmaf(An, nn, Bn));
}

__global__ void __launch_bounds__(32, 4) hh_kernel(
    const float* __restrict__ i_inj,   // [T, N]
    const float* __restrict__ x0,      // [7, N]
    const float* __restrict__ params,  // [28]
    float* __restrict__ out)           // [T, 7, N]
{
    // 592 one-warp blocks = 4/SM = 1/SMSP.
    //   bid <  279       : replica 0 of group bid   (stores V,p,q,n)
    //   279 <= bid < 313 : solo warp (stores all 7)
    //   bid >= 313       : replica 1 of group bid-313 (stores e,f,cac)
    const int bid = blockIdx.x;
    int grp, role;
    if (bid < NGRP) { grp = bid;        role = (bid < NREP) ? 0 : 1; }
    else            { grp = bid - NGRP; role = 2; }
    const bool store_lo = (role != 2);
    const bool store_hi = (role != 0);

    const int pi = grp * 32 + threadIdx.x;
    if (pi >= NPAIR) return;
    const int n2 = 2 * pi;

    // ---- fold constants (identical on replicas -> identical trajectories)
    const float decay_ca = params[0];
    const float rho_ca   = params[1];
    const float p_tau = params[2],  p_scale = params[3],  p_mdp = params[4];
    const float q_tau = params[5],  q_scale = params[6],  q_mdp = params[7];
    const float n_tau = params[8],  n_scale = params[9],  n_mdp = params[10];
    const float f_tau = params[11], f_scale = params[12], f_mdp = params[13];
    const float e_tau = params[14], e_scale = params[15], e_mdp = params[16];
    const float h_alpha = params[17], h_scale = params[18], h_mdp = params[19];
    const float C_m = params[20], g_Ca = params[21], g_Ks = params[22];
    const float g_Kf = params[23], g_L = params[24];
    const float E_Ca = params[25], E_K = params[26], E_L = params[27];

    const float pc1 = 0.5f / p_scale, pc0 = -p_mdp * 0.5f / p_scale;
    const float qc1 = 0.5f / q_scale, qc0 = -q_mdp * 0.5f / q_scale;
    const float nc1 = 0.5f / n_scale, nc0 = -n_mdp * 0.5f / n_scale;
    const float fc1 = 0.5f / f_scale, fc0 = -f_mdp * 0.5f / f_scale;
    const float ec1 = 0.5f / e_scale, ec0 = -e_mdp * 0.5f / e_scale;
    const float hc1 = 0.5f / h_scale, hc0 = -h_mdp * 0.5f / h_scale;

    const float Ap = p_tau / (p_tau + DT), Bp = 0.5f * DT / (p_tau + DT);
    const float Aq = q_tau / (q_tau + DT), Bq = 0.5f * DT / (q_tau + DT);
    const float An = n_tau / (n_tau + DT), Bn = 0.5f * DT / (n_tau + DT);
    const float Af = f_tau / (f_tau + DT), Bf = 0.5f * DT / (f_tau + DT);
    const float Ae = e_tau / (e_tau + DT), Be = 0.5f * DT / (e_tau + DT);

    const float hb = 0.5f * h_alpha, ha = 1.0f - 0.5f * h_alpha;
    const float dtCm  = DT / C_m;
    const float cdec  = 1.0f - DT / decay_ca;

    // dV-scaled conductances
    const float gCad  = g_Ca * dtCm, zk = -gCad * E_Ca;
    const float gKsd  = g_Ks * dtCm, uk = -gKsd * E_K;
    const float rKfKs = g_Kf / g_Ks;
    const float gLd   = g_L * dtCm,  gLdEL = gLd * E_L;
    // cac current term: -rho*dt*g_Ca*(Vnew - E_Ca) = cA*Vnew + cB
    const float cA = -rho_ca * DT * g_Ca;
    const float cB =  rho_ca * DT * g_Ca * E_Ca;

    // ---- state: two adjacent neurons, independent chains a/b
    float Va = x0[0*N_NEUR+n2], Vb = x0[0*N_NEUR+n2+1];
    float pa = x0[1*N_NEUR+n2], pb = x0[1*N_NEUR+n2+1];
    float qa = x0[2*N_NEUR+n2], qb = x0[2*N_NEUR+n2+1];
    float na = x0[3*N_NEUR+n2], nb = x0[3*N_NEUR+n2+1];
    float ea = x0[4*N_NEUR+n2], eb = x0[4*N_NEUR+n2+1];
    float fa = x0[5*N_NEUR+n2], fb = x0[5*N_NEUR+n2+1];
    float ca = x0[6*N_NEUR+n2], cb = x0[6*N_NEUR+n2+1];

    const float* inj = i_inj + n2;
    float* o = out + n2;

    // ---- prefetch UNROLL currents (LDG.64 .ca; replicas hit L2; MLP=10)
    float2 cur[UNROLL];
    #pragma unroll
    for (int u = 0; u < UNROLL; ++u)
        cur[u] = __ldg((const float2*)(inj + u * N_NEUR));
    inj += UNROLL * N_NEUR;

    #pragma unroll 1
    for (int blk = 0; blk < NBLK; ++blk) {
        float2 nxt[UNROLL];
        if (blk < NBLK - 1) {
            #pragma unroll
            for (int u = 0; u < UNROLL; ++u)
                nxt[u] = __ldg((const float2*)(inj + u * N_NEUR));
            inj += UNROLL * N_NEUR;
        }

        #pragma unroll
        for (int u = 0; u < UNROLL; ++u) {
            // two independent scalar chains -> ptxas interleaves, fills stalls
            hh_step(cur[u].x, Va, pa, qa, na, ea, fa, ca,
                    pc1,pc0,qc1,qc0,nc1,nc0,fc1,fc0,ec1,ec0,hc1,hc0,
                    Ap,Bp,Aq,Bq,An,Bn,Af,Bf,Ae,Be, hb,ha,
                    gCad,zk,gKsd,uk,rKfKs,gLd,gLdEL,dtCm,cA,cB,cdec);
            hh_step(cur[u].y, Vb, pb, qb, nb, eb, fb, cb,
                    pc1,pc0,qc1,qc0,nc1,nc0,fc1,fc0,ec1,ec0,hc1,hc0,
                    Ap,Bp,Aq,Bq,An,Bn,Af,Bf,Ae,Be, hb,ha,
                    gCad,zk,gKsd,uk,rKfKs,gLd,gLdEL,dtCm,cA,cB,cdec);

            // role-split streaming stores (STG.64)
            if (store_lo) {
                __stcs((float2*)(o + 0*N_NEUR), make_float2(Va, Vb));
                __stcs((float2*)(o + 1*N_NEUR), make_float2(pa, pb));
                __stcs((float2*)(o + 2*N_NEUR), make_float2(qa, qb));
                __stcs((float2*)(o + 3*N_NEUR), make_float2(na, nb));
            }
            if (store_hi) {
                __stcs((float2*)(o + 4*N_NEUR), make_float2(ea, eb));
                __stcs((float2*)(o + 5*N_NEUR), make_float2(fa, fb));
                __stcs((float2*)(o + 6*N_NEUR), make_float2(ca, cb));
            }
            o += 7 * N_NEUR;
        }

        #pragma unroll
        for (int u = 0; u < UNROLL; ++u)
            cur[u] = nxt[u];
    }
}

extern "C" void kernel_launch(void* const* d_in, const int* in_sizes, int n_in,
                              void* d_out, int out_size) {
    const float* i_inj  = (const float*)d_in[0];
    const float* x0     = (const float*)d_in[1];
    const float* params = (const float*)d_in[2];
    float* out = (float*)d_out;

    // 592 one-warp blocks = 313 groups + 279 replicas -> 1 warp/SMSP balanced
    hh_kernel<<<NGRP + NREP, 32>>>(i_inj, x0, params, out);
}